// round 9
// baseline (speedup 1.0000x reference)
#include <cuda_runtime.h>
#include <math.h>

// Problem constants
#define BB 4
#define SS 2048
#define CC 768
#define HH 12
#define DD 64
#define C3 2304
#define BSROWS (BB * SS)          // 8192
#define HALF_D 32

// ---------------------------------------------------------------------------
// Scratch (device globals; no allocations allowed) — R2 layout
// ---------------------------------------------------------------------------
__device__ float g_qkv[(size_t)BSROWS * C3];            // 8192 x 2304
__device__ float g_q[(size_t)BB * HH * SS * DD];        // (B,H,S,D)
__device__ float g_k[(size_t)BB * HH * SS * DD];
__device__ float g_v[(size_t)BB * HH * SS * DD];
__device__ float g_y[(size_t)BSROWS * CC];              // (B,S,C) pre-proj
__device__ float g_cos[SS * HALF_D];
__device__ float g_sin[SS * HALF_D];

// ---------------------------------------------------------------------------
// RoPE tables (mirrors reference fp32 math)
// ---------------------------------------------------------------------------
__global__ void rope_tables_kernel() {
    int idx = blockIdx.x * blockDim.x + threadIdx.x;
    if (idx >= SS * HALF_D) return;
    int s = idx >> 5;
    int i = idx & 31;
    float theta = 1.0f / powf(10000.0f, (float)i * (1.0f / 32.0f));
    float f = (float)s * theta;
    g_cos[idx] = cosf(f);
    g_sin[idx] = sinf(f);
}

// ---------------------------------------------------------------------------
// fp32 SGEMM tile routine (R2-passing): C[M,N] = A[M,K]*B[K,N], row-major.
// 128x128 tile, K-step 8, 8x8/thread, 256 threads.
// ---------------------------------------------------------------------------
__device__ __forceinline__ void sgemm_tile(
    const float* __restrict__ A, const float* __restrict__ Bm,
    float* __restrict__ Cm, int M, int N, int K)
{
    __shared__ float As[8][128];
    __shared__ float Bs[8][128];

    const int tid = threadIdx.x;
    const int m0 = blockIdx.y * 128;
    const int n0 = blockIdx.x * 128;

    const int arow = tid >> 1;
    const int acol = (tid & 1) * 4;
    const int brow = tid >> 5;
    const int bcol = (tid & 31) * 4;

    const int tx = tid & 15;
    const int ty = tid >> 4;

    float acc[8][8];
#pragma unroll
    for (int i = 0; i < 8; i++)
#pragma unroll
        for (int j = 0; j < 8; j++) acc[i][j] = 0.0f;

    const int ktiles = K >> 3;
    for (int kt = 0; kt < ktiles; kt++) {
        const int k0 = kt << 3;
        float4 av = *(const float4*)&A[(size_t)(m0 + arow) * K + k0 + acol];
        float4 bv = *(const float4*)&Bm[(size_t)(k0 + brow) * N + n0 + bcol];

        As[acol + 0][arow] = av.x;
        As[acol + 1][arow] = av.y;
        As[acol + 2][arow] = av.z;
        As[acol + 3][arow] = av.w;
        *(float4*)&Bs[brow][bcol] = bv;
        __syncthreads();

#pragma unroll
        for (int kk = 0; kk < 8; kk++) {
            float4 a0 = *(const float4*)&As[kk][ty * 8];
            float4 a1 = *(const float4*)&As[kk][ty * 8 + 4];
            float4 b0 = *(const float4*)&Bs[kk][tx * 8];
            float4 b1 = *(const float4*)&Bs[kk][tx * 8 + 4];
            float ar[8] = {a0.x, a0.y, a0.z, a0.w, a1.x, a1.y, a1.z, a1.w};
            float br[8] = {b0.x, b0.y, b0.z, b0.w, b1.x, b1.y, b1.z, b1.w};
#pragma unroll
            for (int i = 0; i < 8; i++)
#pragma unroll
                for (int j = 0; j < 8; j++)
                    acc[i][j] = fmaf(ar[i], br[j], acc[i][j]);
        }
        __syncthreads();
    }

#pragma unroll
    for (int i = 0; i < 8; i++) {
        float* crow = Cm + (size_t)(m0 + ty * 8 + i) * N + n0 + tx * 8;
        float4 c0 = {acc[i][0], acc[i][1], acc[i][2], acc[i][3]};
        float4 c1 = {acc[i][4], acc[i][5], acc[i][6], acc[i][7]};
        *(float4*)crow = c0;
        *(float4*)(crow + 4) = c1;
    }
}

__global__ __launch_bounds__(256) void sgemm_qkv_kernel(
    const float* __restrict__ x, const float* __restrict__ Wqkv)
{
    sgemm_tile(x, Wqkv, g_qkv, BSROWS, C3, CC);
}

__global__ __launch_bounds__(256) void sgemm_proj_kernel(
    const float* __restrict__ Wproj, float* __restrict__ out)
{
    sgemm_tile(g_y, Wproj, out, BSROWS, CC, CC);
}

// ---------------------------------------------------------------------------
// RoPE + split + transpose (R2, unchanged)
// ---------------------------------------------------------------------------
__global__ void rope_split_kernel() {
    int idx = blockIdx.x * blockDim.x + threadIdx.x;
    const int total = BB * SS * CC;
    if (idx >= total) return;

    int c = idx % CC;
    int bs = idx / CC;
    int srow = bs % SS;
    int b = bs / SS;
    int h = c >> 6;
    int d = c & 63;

    const float* row = g_qkv + (size_t)bs * C3;
    float cosv = g_cos[srow * HALF_D + (d & 31)];
    float sinv = g_sin[srow * HALF_D + (d & 31)];

    float qv = row[c];
    float kv = row[CC + c];
    float vv = row[2 * CC + c];

    int other = (d < HALF_D) ? (c + HALF_D) : (c - HALF_D);
    float q_other = row[other];
    float k_other = row[CC + other];

    float qo, ko;
    if (d < HALF_D) {
        qo = qv * cosv - q_other * sinv;
        ko = kv * cosv - k_other * sinv;
    } else {
        qo = qv * cosv + q_other * sinv;
        ko = kv * cosv + k_other * sinv;
    }

    size_t outp = ((size_t)(b * HH + h) * SS + srow) * DD + d;
    g_q[outp] = qo;
    g_k[outp] = ko;
    g_v[outp] = vv;
}

// ---------------------------------------------------------------------------
// Flash attention, fp32, split-D: 128 threads/block, 2 threads per query row
// (each owns 32 of 64 dims). Same tile logic as R2 (64-row q-tile, 64-key
// kv-tile, reversed launch for diag-heavy-first).
// ---------------------------------------------------------------------------
__global__ __launch_bounds__(128) void attn_kernel() {
    const int qt = gridDim.x - 1 - blockIdx.x;     // query tile (64 rows)
    const int bh = blockIdx.y;
    const int b = bh / HH;
    const int h = bh % HH;
    const int tid = threadIdx.x;
    const int half = tid & 1;                       // which 32-dim half
    const int rloc = tid >> 1;                      // row within tile 0..63

    const size_t base = (size_t)bh * SS * DD;
    const int mrow = qt * 64 + rloc;

    // log2(e) * D^-0.5 folded into Q
    const float sc = 0.125f * 1.4426950408889634f;

    float qr[32];
    {
        const float4* qp = (const float4*)(g_q + base + (size_t)mrow * DD + half * 32);
#pragma unroll
        for (int i = 0; i < 8; i++) {
            float4 t4 = qp[i];
            qr[4 * i + 0] = t4.x * sc;
            qr[4 * i + 1] = t4.y * sc;
            qr[4 * i + 2] = t4.z * sc;
            qr[4 * i + 3] = t4.w * sc;
        }
    }

    float o[32];
#pragma unroll
    for (int i = 0; i < 32; i++) o[i] = 0.0f;
    float mi = -3.0e38f;
    float li = 0.0f;

    __shared__ float Ks[64 * 64];
    __shared__ float Vs[64 * 64];
    float4* kd = (float4*)Ks;
    float4* vd = (float4*)Vs;

    for (int t = 0; t <= qt; t++) {
        const float4* ksrc = (const float4*)(g_k + base + (size_t)t * 64 * DD);
        const float4* vsrc = (const float4*)(g_v + base + (size_t)t * 64 * DD);
        __syncthreads();
#pragma unroll
        for (int i = 0; i < 8; i++) {
            kd[i * 128 + tid] = ksrc[i * 128 + tid];
            vd[i * 128 + tid] = vsrc[i * 128 + tid];
        }
        __syncthreads();

        const bool diag = (t == qt);

        for (int jc = 0; jc < 64; jc += 8) {
            float s[8];
#pragma unroll
            for (int jj = 0; jj < 8; jj++) {
                const float4* kr = (const float4*)(Ks + (jc + jj) * 64 + half * 32);
                float a0 = 0.f, a1 = 0.f, a2 = 0.f, a3 = 0.f;
#pragma unroll
                for (int d4 = 0; d4 < 8; d4++) {
                    float4 kk = kr[d4];
                    a0 = fmaf(qr[4 * d4 + 0], kk.x, a0);
                    a1 = fmaf(qr[4 * d4 + 1], kk.y, a1);
                    a2 = fmaf(qr[4 * d4 + 2], kk.z, a2);
                    a3 = fmaf(qr[4 * d4 + 3], kk.w, a3);
                }
                s[jj] = (a0 + a1) + (a2 + a3);
            }
            // combine the two halves of each dot product (pair lanes L, L^1)
#pragma unroll
            for (int jj = 0; jj < 8; jj++) {
                s[jj] += __shfl_xor_sync(0xffffffffu, s[jj], 1);
                if (diag && (jc + jj) > rloc) s[jj] = -3.0e38f;
            }

            float mnew = mi;
#pragma unroll
            for (int jj = 0; jj < 8; jj++) mnew = fmaxf(mnew, s[jj]);

            float cfac = exp2f(mi - mnew);
            mi = mnew;
            li *= cfac;
#pragma unroll
            for (int d = 0; d < 32; d++) o[d] *= cfac;

            float p[8];
#pragma unroll
            for (int jj = 0; jj < 8; jj++) {
                p[jj] = exp2f(s[jj] - mi);
                li += p[jj];
            }

#pragma unroll
            for (int jj = 0; jj < 8; jj++) {
                const float4* vr = (const float4*)(Vs + (jc + jj) * 64 + half * 32);
#pragma unroll
                for (int d4 = 0; d4 < 8; d4++) {
                    float4 vv = vr[d4];
                    o[4 * d4 + 0] = fmaf(p[jj], vv.x, o[4 * d4 + 0]);
                    o[4 * d4 + 1] = fmaf(p[jj], vv.y, o[4 * d4 + 1]);
                    o[4 * d4 + 2] = fmaf(p[jj], vv.z, o[4 * d4 + 2]);
                    o[4 * d4 + 3] = fmaf(p[jj], vv.w, o[4 * d4 + 3]);
                }
            }
        }
    }

    const float inv = 1.0f / li;
    float* yp = g_y + ((size_t)(b * SS + mrow)) * CC + h * DD + half * 32;
#pragma unroll
    for (int i = 0; i < 8; i++) {
        float4 t4;
        t4.x = o[4 * i + 0] * inv;
        t4.y = o[4 * i + 1] * inv;
        t4.z = o[4 * i + 2] * inv;
        t4.w = o[4 * i + 3] * inv;
        *(float4*)(yp + 4 * i) = t4;
    }
}

// ---------------------------------------------------------------------------
// Launch — kernel launches ONLY.
// ---------------------------------------------------------------------------
extern "C" void kernel_launch(void* const* d_in, const int* in_sizes, int n_in,
                              void* d_out, int out_size)
{
    const float* x     = (const float*)d_in[0];   // (B,S,C) = 8192x768
    const float* Wqkv  = (const float*)d_in[1];   // 768x2304
    const float* Wproj = (const float*)d_in[2];   // 768x768
    float* out = (float*)d_out;                   // (B,S,C)

    // 1. RoPE tables
    rope_tables_kernel<<<(SS * HALF_D + 255) / 256, 256>>>();

    // 2. QKV GEMM: (8192x768) @ (768x2304)
    {
        dim3 grid(C3 / 128, BSROWS / 128);
        sgemm_qkv_kernel<<<grid, 256>>>(x, Wqkv);
    }

    // 3. RoPE + split + transpose
    rope_split_kernel<<<(BB * SS * CC + 255) / 256, 256>>>();

    // 4. Flash attention (split-D, 128 threads/block)
    {
        dim3 grid(SS / 64, BB * HH);
        attn_kernel<<<grid, 128>>>();
    }

    // 5. Output projection: (8192x768) @ (768x768)
    {
        dim3 grid(CC / 128, BSROWS / 128);
        sgemm_proj_kernel<<<grid, 256>>>(Wproj, out);
    }
}

// round 12
// speedup vs baseline: 1.3129x; 1.3129x over previous
#include <cuda_runtime.h>
#include <math.h>

// Problem constants
#define BB 4
#define SS 2048
#define CC 768
#define HH 12
#define DD 64
#define C3 2304
#define BSROWS (BB * SS)          // 8192
#define HALF_D 32

// ---------------------------------------------------------------------------
// Scratch (device globals; no allocations allowed) — R2 layout
// ---------------------------------------------------------------------------
__device__ float g_qkv[(size_t)BSROWS * C3];            // 8192 x 2304
__device__ float g_q[(size_t)BB * HH * SS * DD];        // (B,H,S,D)
__device__ float g_k[(size_t)BB * HH * SS * DD];
__device__ float g_v[(size_t)BB * HH * SS * DD];
__device__ float g_y[(size_t)BSROWS * CC];              // (B,S,C) pre-proj
__device__ float g_cos[SS * HALF_D];
__device__ float g_sin[SS * HALF_D];

// ---------------------------------------------------------------------------
// RoPE tables (mirrors reference fp32 math)
// ---------------------------------------------------------------------------
__global__ void rope_tables_kernel() {
    int idx = blockIdx.x * blockDim.x + threadIdx.x;
    if (idx >= SS * HALF_D) return;
    int s = idx >> 5;
    int i = idx & 31;
    float theta = 1.0f / powf(10000.0f, (float)i * (1.0f / 32.0f));
    float f = (float)s * theta;
    g_cos[idx] = cosf(f);
    g_sin[idx] = sinf(f);
}

// ---------------------------------------------------------------------------
// fp32 SGEMM tile routine (R2-passing): C[M,N] = A[M,K]*B[K,N], row-major.
// ---------------------------------------------------------------------------
__device__ __forceinline__ void sgemm_tile(
    const float* __restrict__ A, const float* __restrict__ Bm,
    float* __restrict__ Cm, int M, int N, int K)
{
    __shared__ float As[8][128];
    __shared__ float Bs[8][128];

    const int tid = threadIdx.x;
    const int m0 = blockIdx.y * 128;
    const int n0 = blockIdx.x * 128;

    const int arow = tid >> 1;
    const int acol = (tid & 1) * 4;
    const int brow = tid >> 5;
    const int bcol = (tid & 31) * 4;

    const int tx = tid & 15;
    const int ty = tid >> 4;

    float acc[8][8];
#pragma unroll
    for (int i = 0; i < 8; i++)
#pragma unroll
        for (int j = 0; j < 8; j++) acc[i][j] = 0.0f;

    const int ktiles = K >> 3;
    for (int kt = 0; kt < ktiles; kt++) {
        const int k0 = kt << 3;
        float4 av = *(const float4*)&A[(size_t)(m0 + arow) * K + k0 + acol];
        float4 bv = *(const float4*)&Bm[(size_t)(k0 + brow) * N + n0 + bcol];

        As[acol + 0][arow] = av.x;
        As[acol + 1][arow] = av.y;
        As[acol + 2][arow] = av.z;
        As[acol + 3][arow] = av.w;
        *(float4*)&Bs[brow][bcol] = bv;
        __syncthreads();

#pragma unroll
        for (int kk = 0; kk < 8; kk++) {
            float4 a0 = *(const float4*)&As[kk][ty * 8];
            float4 a1 = *(const float4*)&As[kk][ty * 8 + 4];
            float4 b0 = *(const float4*)&Bs[kk][tx * 8];
            float4 b1 = *(const float4*)&Bs[kk][tx * 8 + 4];
            float ar[8] = {a0.x, a0.y, a0.z, a0.w, a1.x, a1.y, a1.z, a1.w};
            float br[8] = {b0.x, b0.y, b0.z, b0.w, b1.x, b1.y, b1.z, b1.w};
#pragma unroll
            for (int i = 0; i < 8; i++)
#pragma unroll
                for (int j = 0; j < 8; j++)
                    acc[i][j] = fmaf(ar[i], br[j], acc[i][j]);
        }
        __syncthreads();
    }

#pragma unroll
    for (int i = 0; i < 8; i++) {
        float* crow = Cm + (size_t)(m0 + ty * 8 + i) * N + n0 + tx * 8;
        float4 c0 = {acc[i][0], acc[i][1], acc[i][2], acc[i][3]};
        float4 c1 = {acc[i][4], acc[i][5], acc[i][6], acc[i][7]};
        *(float4*)crow = c0;
        *(float4*)(crow + 4) = c1;
    }
}

__global__ __launch_bounds__(256) void sgemm_qkv_kernel(
    const float* __restrict__ x, const float* __restrict__ Wqkv)
{
    sgemm_tile(x, Wqkv, g_qkv, BSROWS, C3, CC);
}

__global__ __launch_bounds__(256) void sgemm_proj_kernel(
    const float* __restrict__ Wproj, float* __restrict__ out)
{
    sgemm_tile(g_y, Wproj, out, BSROWS, CC, CC);
}

// ---------------------------------------------------------------------------
// RoPE + split + transpose (R2, unchanged)
// ---------------------------------------------------------------------------
__global__ void rope_split_kernel() {
    int idx = blockIdx.x * blockDim.x + threadIdx.x;
    const int total = BB * SS * CC;
    if (idx >= total) return;

    int c = idx % CC;
    int bs = idx / CC;
    int srow = bs % SS;
    int b = bs / SS;
    int h = c >> 6;
    int d = c & 63;

    const float* row = g_qkv + (size_t)bs * C3;
    float cosv = g_cos[srow * HALF_D + (d & 31)];
    float sinv = g_sin[srow * HALF_D + (d & 31)];

    float qv = row[c];
    float kv = row[CC + c];
    float vv = row[2 * CC + c];

    int other = (d < HALF_D) ? (c + HALF_D) : (c - HALF_D);
    float q_other = row[other];
    float k_other = row[CC + other];

    float qo, ko;
    if (d < HALF_D) {
        qo = qv * cosv - q_other * sinv;
        ko = kv * cosv - k_other * sinv;
    } else {
        qo = qv * cosv + q_other * sinv;
        ko = kv * cosv + k_other * sinv;
    }

    size_t outp = ((size_t)(b * HH + h) * SS + srow) * DD + d;
    g_q[outp] = qo;
    g_k[outp] = ko;
    g_v[outp] = vv;
}

// ---------------------------------------------------------------------------
// Flash attention, fp32, register-blocked gemms.
// Block = 64 threads (8 tx x 8 ty). Q-tile 64 rows, key-tile 32.
// QK: thread tile 8q x 4k.  PV: thread tile 8q x 8d.
// ---------------------------------------------------------------------------
__global__ __launch_bounds__(64) void attn_kernel() {
    const int qt = gridDim.x - 1 - blockIdx.x;     // query tile (64 rows)
    const int bh = blockIdx.y;
    const int b = bh / HH;
    const int h = bh % HH;
    const int tid = threadIdx.x;
    const int tx = tid & 7;
    const int ty = tid >> 3;

    __shared__ float Qt[64][68];   // [d][q]
    __shared__ float Kt[64][36];   // [d][k]
    __shared__ float Vs[32][68];   // [k][d]
    __shared__ float Ps[64][33];   // [q][k]  pad 33 -> conflict-free columns

    const size_t base = (size_t)bh * SS * DD;
    const float sc = 0.125f * 1.4426950408889634f;  // D^-0.5 * log2(e)

    // Load Q tile transposed (thread tid owns query row qt*64+tid)
    {
        const float4* qp = (const float4*)(g_q + base + (size_t)(qt * 64 + tid) * DD);
#pragma unroll
        for (int i = 0; i < 16; i++) {
            float4 v = qp[i];
            Qt[4 * i + 0][tid] = v.x * sc;
            Qt[4 * i + 1][tid] = v.y * sc;
            Qt[4 * i + 2][tid] = v.z * sc;
            Qt[4 * i + 3][tid] = v.w * sc;
        }
    }

    float o[8][8];
#pragma unroll
    for (int i = 0; i < 8; i++)
#pragma unroll
        for (int j = 0; j < 8; j++) o[i][j] = 0.0f;
    float m[8], l[8];
#pragma unroll
    for (int i = 0; i < 8; i++) { m[i] = -3.0e38f; l[i] = 0.0f; }

    const int ntiles = 2 * qt + 2;      // 32-key tiles
    const int qbase = qt * 64;

    for (int t = 0; t < ntiles; t++) {
        __syncthreads();
        // Load K (transposed) and V tiles: 32 key rows, 2 warps x half-row
        {
            const int krow = (tid & 31);
            const int half = tid >> 5;          // 0/1
            const float* kp = g_k + base + (size_t)(t * 32 + krow) * DD + half * 32;
            const float* vp = g_v + base + (size_t)(t * 32 + krow) * DD + half * 32;
#pragma unroll
            for (int i = 0; i < 8; i++) {
                float4 kv = *(const float4*)(kp + 4 * i);
                const int d = half * 32 + 4 * i;
                Kt[d + 0][krow] = kv.x;
                Kt[d + 1][krow] = kv.y;
                Kt[d + 2][krow] = kv.z;
                Kt[d + 3][krow] = kv.w;
                *(float4*)&Vs[krow][half * 32 + 4 * i] = *(const float4*)(vp + 4 * i);
            }
        }
        __syncthreads();

        // ---- QK^T: s[8q][4k] ----
        float s[8][4];
#pragma unroll
        for (int i = 0; i < 8; i++)
#pragma unroll
            for (int j = 0; j < 4; j++) s[i][j] = 0.0f;

#pragma unroll 4
        for (int kk = 0; kk < 64; kk++) {
            float4 a0 = *(const float4*)&Qt[kk][ty * 8];
            float4 a1 = *(const float4*)&Qt[kk][ty * 8 + 4];
            float4 bv = *(const float4*)&Kt[kk][tx * 4];
            float ar[8] = {a0.x, a0.y, a0.z, a0.w, a1.x, a1.y, a1.z, a1.w};
            float br[4] = {bv.x, bv.y, bv.z, bv.w};
#pragma unroll
            for (int i = 0; i < 8; i++)
#pragma unroll
                for (int j = 0; j < 4; j++)
                    s[i][j] = fmaf(ar[i], br[j], s[i][j]);
        }

        // ---- causal mask (only partial on last two tiles) ----
        if (t >= 2 * qt) {
            const int kb = t * 32 + tx * 4;
#pragma unroll
            for (int i = 0; i < 8; i++) {
                const int r = qbase + ty * 8 + i;
#pragma unroll
                for (int j = 0; j < 4; j++)
                    if (kb + j > r) s[i][j] = -3.0e38f;
            }
        }

        // ---- online softmax (row groups = 8 lanes sharing ty) ----
#pragma unroll
        for (int i = 0; i < 8; i++) {
            float mx = fmaxf(fmaxf(s[i][0], s[i][1]), fmaxf(s[i][2], s[i][3]));
            mx = fmaxf(mx, __shfl_xor_sync(0xffffffffu, mx, 1));
            mx = fmaxf(mx, __shfl_xor_sync(0xffffffffu, mx, 2));
            mx = fmaxf(mx, __shfl_xor_sync(0xffffffffu, mx, 4));
            float mnew = fmaxf(m[i], mx);
            float cf = exp2f(m[i] - mnew);
            m[i] = mnew;
            float rs = 0.0f;
#pragma unroll
            for (int j = 0; j < 4; j++) {
                s[i][j] = exp2f(s[i][j] - mnew);
                rs += s[i][j];
            }
            rs += __shfl_xor_sync(0xffffffffu, rs, 1);
            rs += __shfl_xor_sync(0xffffffffu, rs, 2);
            rs += __shfl_xor_sync(0xffffffffu, rs, 4);
            l[i] = l[i] * cf + rs;
#pragma unroll
            for (int j = 0; j < 8; j++) o[i][j] *= cf;
        }

        // ---- write P (rotated column order -> conflict-free) ----
#pragma unroll
        for (int jj = 0; jj < 4; jj++) {
            const int j = (jj + tx + ty) & 3;
#pragma unroll
            for (int i = 0; i < 8; i++)
                Ps[ty * 8 + i][tx * 4 + j] = s[i][j];
        }
        __syncthreads();

        // ---- PV: o[8q][8d] += P[8q][32k] @ V[32k][8d] ----
#pragma unroll 4
        for (int kk = 0; kk < 32; kk++) {
            float pr[8];
#pragma unroll
            for (int i = 0; i < 8; i++) pr[i] = Ps[ty * 8 + i][kk];
            float4 v0 = *(const float4*)&Vs[kk][tx * 8];
            float4 v1 = *(const float4*)&Vs[kk][tx * 8 + 4];
            float vr[8] = {v0.x, v0.y, v0.z, v0.w, v1.x, v1.y, v1.z, v1.w};
#pragma unroll
            for (int i = 0; i < 8; i++)
#pragma unroll
                for (int j = 0; j < 8; j++)
                    o[i][j] = fmaf(pr[i], vr[j], o[i][j]);
        }
    }

    // ---- writeout ----
#pragma unroll
    for (int i = 0; i < 8; i++) {
        const float inv = 1.0f / l[i];
        const int row = qbase + ty * 8 + i;
        float* yp = g_y + (size_t)(b * SS + row) * CC + h * DD + tx * 8;
        float4 c0 = {o[i][0] * inv, o[i][1] * inv, o[i][2] * inv, o[i][3] * inv};
        float4 c1 = {o[i][4] * inv, o[i][5] * inv, o[i][6] * inv, o[i][7] * inv};
        *(float4*)yp = c0;
        *(float4*)(yp + 4) = c1;
    }
}

// ---------------------------------------------------------------------------
// Launch — kernel launches ONLY.
// ---------------------------------------------------------------------------
extern "C" void kernel_launch(void* const* d_in, const int* in_sizes, int n_in,
                              void* d_out, int out_size)
{
    const float* x     = (const float*)d_in[0];   // (B,S,C)
    const float* Wqkv  = (const float*)d_in[1];   // 768x2304
    const float* Wproj = (const float*)d_in[2];   // 768x768
    float* out = (float*)d_out;                   // (B,S,C)

    // 1. RoPE tables
    rope_tables_kernel<<<(SS * HALF_D + 255) / 256, 256>>>();

    // 2. QKV GEMM: (8192x768) @ (768x2304)
    {
        dim3 grid(C3 / 128, BSROWS / 128);
        sgemm_qkv_kernel<<<grid, 256>>>(x, Wqkv);
    }

    // 3. RoPE + split + transpose
    rope_split_kernel<<<(BB * SS * CC + 255) / 256, 256>>>();

    // 4. Flash attention (register-blocked)
    {
        dim3 grid(SS / 64, BB * HH);
        attn_kernel<<<grid, 64>>>();
    }

    // 5. Output projection: (8192x768) @ (768x768)
    {
        dim3 grid(CC / 128, BSROWS / 128);
        sgemm_proj_kernel<<<grid, 256>>>(Wproj, out);
    }
}

// round 13
// speedup vs baseline: 1.3320x; 1.0146x over previous
#include <cuda_runtime.h>
#include <math.h>

// Problem constants
#define BB 4
#define SS 2048
#define CC 768
#define HH 12
#define DD 64
#define C3 2304
#define BSROWS (BB * SS)          // 8192
#define HALF_D 32

// ---------------------------------------------------------------------------
// Scratch (device globals; no allocations allowed)
// ---------------------------------------------------------------------------
__device__ float g_qkv[(size_t)BSROWS * C3];            // 8192 x 2304
__device__ float g_q[(size_t)BB * HH * SS * DD];        // (B,H,S,D)
__device__ float g_k[(size_t)BB * HH * SS * DD];
__device__ float g_v[(size_t)BB * HH * SS * DD];
__device__ float g_y[(size_t)BSROWS * CC];              // (B,S,C) pre-proj
__device__ float g_cos[SS * HALF_D];
__device__ float g_sin[SS * HALF_D];

// ---------------------------------------------------------------------------
// RoPE tables (mirrors reference fp32 math)
// ---------------------------------------------------------------------------
__global__ void rope_tables_kernel() {
    int idx = blockIdx.x * blockDim.x + threadIdx.x;
    if (idx >= SS * HALF_D) return;
    int s = idx >> 5;
    int i = idx & 31;
    float theta = 1.0f / powf(10000.0f, (float)i * (1.0f / 32.0f));
    float f = (float)s * theta;
    g_cos[idx] = cosf(f);
    g_sin[idx] = sinf(f);
}

// ---------------------------------------------------------------------------
// fp32 SGEMM: C[M,N] = A[M,K]*B[K,N], row-major. 128x128 tile, K-step 8,
// 8x8/thread, 256 threads, register-prefetch pipeline (LDG hidden by FMAs).
// ---------------------------------------------------------------------------
__device__ __forceinline__ void sgemm_tile(
    const float* __restrict__ A, const float* __restrict__ Bm,
    float* __restrict__ Cm, int M, int N, int K)
{
    __shared__ float As[8][128];
    __shared__ float Bs[8][128];

    const int tid = threadIdx.x;
    const int m0 = blockIdx.y * 128;
    const int n0 = blockIdx.x * 128;

    const int arow = tid >> 1;
    const int acol = (tid & 1) * 4;
    const int brow = tid >> 5;
    const int bcol = (tid & 31) * 4;

    const int tx = tid & 15;
    const int ty = tid >> 4;

    float acc[8][8];
#pragma unroll
    for (int i = 0; i < 8; i++)
#pragma unroll
        for (int j = 0; j < 8; j++) acc[i][j] = 0.0f;

    const int ktiles = K >> 3;

    // Prefetch kt=0
    float4 av = *(const float4*)&A[(size_t)(m0 + arow) * K + acol];
    float4 bv = *(const float4*)&Bm[(size_t)brow * N + n0 + bcol];

    for (int kt = 0; kt < ktiles; kt++) {
        if (kt > 0) __syncthreads();

        As[acol + 0][arow] = av.x;
        As[acol + 1][arow] = av.y;
        As[acol + 2][arow] = av.z;
        As[acol + 3][arow] = av.w;
        *(float4*)&Bs[brow][bcol] = bv;
        __syncthreads();

        if (kt + 1 < ktiles) {
            const int k0 = (kt + 1) << 3;
            av = *(const float4*)&A[(size_t)(m0 + arow) * K + k0 + acol];
            bv = *(const float4*)&Bm[(size_t)(k0 + brow) * N + n0 + bcol];
        }

#pragma unroll
        for (int kk = 0; kk < 8; kk++) {
            float4 a0 = *(const float4*)&As[kk][ty * 8];
            float4 a1 = *(const float4*)&As[kk][ty * 8 + 4];
            float4 b0 = *(const float4*)&Bs[kk][tx * 8];
            float4 b1 = *(const float4*)&Bs[kk][tx * 8 + 4];
            float ar[8] = {a0.x, a0.y, a0.z, a0.w, a1.x, a1.y, a1.z, a1.w};
            float br[8] = {b0.x, b0.y, b0.z, b0.w, b1.x, b1.y, b1.z, b1.w};
#pragma unroll
            for (int i = 0; i < 8; i++)
#pragma unroll
                for (int j = 0; j < 8; j++)
                    acc[i][j] = fmaf(ar[i], br[j], acc[i][j]);
        }
    }

#pragma unroll
    for (int i = 0; i < 8; i++) {
        float* crow = Cm + (size_t)(m0 + ty * 8 + i) * N + n0 + tx * 8;
        float4 c0 = {acc[i][0], acc[i][1], acc[i][2], acc[i][3]};
        float4 c1 = {acc[i][4], acc[i][5], acc[i][6], acc[i][7]};
        *(float4*)crow = c0;
        *(float4*)(crow + 4) = c1;
    }
}

__global__ __launch_bounds__(256) void sgemm_qkv_kernel(
    const float* __restrict__ x, const float* __restrict__ Wqkv)
{
    sgemm_tile(x, Wqkv, g_qkv, BSROWS, C3, CC);
}

__global__ __launch_bounds__(256) void sgemm_proj_kernel(
    const float* __restrict__ Wproj, float* __restrict__ out)
{
    sgemm_tile(g_y, Wproj, out, BSROWS, CC, CC);
}

// ---------------------------------------------------------------------------
// RoPE + split + transpose (unchanged)
// ---------------------------------------------------------------------------
__global__ void rope_split_kernel() {
    int idx = blockIdx.x * blockDim.x + threadIdx.x;
    const int total = BB * SS * CC;
    if (idx >= total) return;

    int c = idx % CC;
    int bs = idx / CC;
    int srow = bs % SS;
    int b = bs / SS;
    int h = c >> 6;
    int d = c & 63;

    const float* row = g_qkv + (size_t)bs * C3;
    float cosv = g_cos[srow * HALF_D + (d & 31)];
    float sinv = g_sin[srow * HALF_D + (d & 31)];

    float qv = row[c];
    float kv = row[CC + c];
    float vv = row[2 * CC + c];

    int other = (d < HALF_D) ? (c + HALF_D) : (c - HALF_D);
    float q_other = row[other];
    float k_other = row[CC + other];

    float qo, ko;
    if (d < HALF_D) {
        qo = qv * cosv - q_other * sinv;
        ko = kv * cosv - k_other * sinv;
    } else {
        qo = qv * cosv + q_other * sinv;
        ko = kv * cosv + k_other * sinv;
    }

    size_t outp = ((size_t)(b * HH + h) * SS + srow) * DD + d;
    g_q[outp] = qo;
    g_k[outp] = ko;
    g_v[outp] = vv;
}

// ---------------------------------------------------------------------------
// Flash attention, fp32, register-blocked + software-pipelined K/V loads.
// Block = 64 threads (8 tx x 8 ty). Q-tile 64 rows, key-tile 32.
// QK: thread tile 8q x 4k.  PV: thread tile 8q x 8d with float4 P loads.
// ---------------------------------------------------------------------------
__global__ __launch_bounds__(64) void attn_kernel() {
    const int qt = gridDim.x - 1 - blockIdx.x;     // query tile (64 rows)
    const int bh = blockIdx.y;
    const int b = bh / HH;
    const int h = bh % HH;
    const int tid = threadIdx.x;
    const int tx = tid & 7;
    const int ty = tid >> 3;
    const int krow = tid & 31;
    const int half = tid >> 5;

    __shared__ float Qt[64][68];   // [d][q]
    __shared__ float Kt[64][36];   // [d][k]
    __shared__ float Vs[32][68];   // [k][d]
    __shared__ float Ps[64][36];   // [q][k] pad 36 -> aligned float4 rows

    const size_t base = (size_t)bh * SS * DD;
    const float sc = 0.125f * 1.4426950408889634f;  // D^-0.5 * log2(e)

    // Load Q tile transposed (thread tid owns query row qt*64+tid)
    {
        const float4* qp = (const float4*)(g_q + base + (size_t)(qt * 64 + tid) * DD);
#pragma unroll
        for (int i = 0; i < 16; i++) {
            float4 v = qp[i];
            Qt[4 * i + 0][tid] = v.x * sc;
            Qt[4 * i + 1][tid] = v.y * sc;
            Qt[4 * i + 2][tid] = v.z * sc;
            Qt[4 * i + 3][tid] = v.w * sc;
        }
    }

    float o[8][8];
#pragma unroll
    for (int i = 0; i < 8; i++)
#pragma unroll
        for (int j = 0; j < 8; j++) o[i][j] = 0.0f;
    float m[8], l[8];
#pragma unroll
    for (int i = 0; i < 8; i++) { m[i] = -3.0e38f; l[i] = 0.0f; }

    const int ntiles = 2 * qt + 2;      // 32-key tiles
    const int qbase = qt * 64;

    // Prefetch K tile 0 into registers (half-row of 32 floats)
    float4 kr[8];
    {
        const float* kp = g_k + base + (size_t)krow * DD + half * 32;
#pragma unroll
        for (int i = 0; i < 8; i++) kr[i] = *(const float4*)(kp + 4 * i);
    }

    for (int t = 0; t < ntiles; t++) {
        __syncthreads();               // previous tile's consumers done

        // Store K tile (transposed scatter, conflict-free)
#pragma unroll
        for (int i = 0; i < 8; i++) {
            const int d = half * 32 + 4 * i;
            Kt[d + 0][krow] = kr[i].x;
            Kt[d + 1][krow] = kr[i].y;
            Kt[d + 2][krow] = kr[i].z;
            Kt[d + 3][krow] = kr[i].w;
        }

        // Prefetch V tile t (LDG overlaps QK compute below)
        float4 vg[8];
        {
            const float* vp = g_v + base + (size_t)(t * 32 + krow) * DD + half * 32;
#pragma unroll
            for (int i = 0; i < 8; i++) vg[i] = *(const float4*)(vp + 4 * i);
        }
        __syncthreads();               // Kt visible

        // ---- QK^T: s[8q][4k] ----
        float s[8][4];
#pragma unroll
        for (int i = 0; i < 8; i++)
#pragma unroll
            for (int j = 0; j < 4; j++) s[i][j] = 0.0f;

#pragma unroll 4
        for (int kk = 0; kk < 64; kk++) {
            float4 a0 = *(const float4*)&Qt[kk][ty * 8];
            float4 a1 = *(const float4*)&Qt[kk][ty * 8 + 4];
            float4 bv = *(const float4*)&Kt[kk][tx * 4];
            float ar[8] = {a0.x, a0.y, a0.z, a0.w, a1.x, a1.y, a1.z, a1.w};
            float br[4] = {bv.x, bv.y, bv.z, bv.w};
#pragma unroll
            for (int i = 0; i < 8; i++)
#pragma unroll
                for (int j = 0; j < 4; j++)
                    s[i][j] = fmaf(ar[i], br[j], s[i][j]);
        }

        // ---- causal mask (partial only on last two tiles) ----
        if (t >= 2 * qt) {
            const int kb = t * 32 + tx * 4;
#pragma unroll
            for (int i = 0; i < 8; i++) {
                const int r = qbase + ty * 8 + i;
#pragma unroll
                for (int j = 0; j < 4; j++)
                    if (kb + j > r) s[i][j] = -3.0e38f;
            }
        }

        // ---- online softmax (8 lanes per row group) ----
#pragma unroll
        for (int i = 0; i < 8; i++) {
            float mx = fmaxf(fmaxf(s[i][0], s[i][1]), fmaxf(s[i][2], s[i][3]));
            mx = fmaxf(mx, __shfl_xor_sync(0xffffffffu, mx, 1));
            mx = fmaxf(mx, __shfl_xor_sync(0xffffffffu, mx, 2));
            mx = fmaxf(mx, __shfl_xor_sync(0xffffffffu, mx, 4));
            float mnew = fmaxf(m[i], mx);
            float cf = exp2f(m[i] - mnew);
            m[i] = mnew;
            float rs = 0.0f;
#pragma unroll
            for (int j = 0; j < 4; j++) {
                s[i][j] = exp2f(s[i][j] - mnew);
                rs += s[i][j];
            }
            rs += __shfl_xor_sync(0xffffffffu, rs, 1);
            rs += __shfl_xor_sync(0xffffffffu, rs, 2);
            rs += __shfl_xor_sync(0xffffffffu, rs, 4);
            l[i] = l[i] * cf + rs;
#pragma unroll
            for (int j = 0; j < 8; j++) o[i][j] *= cf;
        }

        // ---- write P (rotated -> conflict-free) ----
#pragma unroll
        for (int jj = 0; jj < 4; jj++) {
            const int j = (jj + ty) & 3;
#pragma unroll
            for (int i = 0; i < 8; i++)
                Ps[ty * 8 + i][tx * 4 + j] = s[i][j];
        }

        // Prefetch K tile t+1 (LDG overlaps PV compute below)
        if (t + 1 < ntiles) {
            const float* kp = g_k + base + (size_t)((t + 1) * 32 + krow) * DD + half * 32;
#pragma unroll
            for (int i = 0; i < 8; i++) kr[i] = *(const float4*)(kp + 4 * i);
        }

        // Store V tile (vg arrived during QK)
#pragma unroll
        for (int i = 0; i < 8; i++)
            *(float4*)&Vs[krow][half * 32 + 4 * i] = vg[i];

        __syncthreads();               // Vs + Ps visible

        // ---- PV: o[8q][8d] += P[8q][32k] @ V[32k][8d], float4 P loads ----
#pragma unroll
        for (int kk4 = 0; kk4 < 8; kk4++) {
            float4 ps4[8];
#pragma unroll
            for (int i = 0; i < 8; i++)
                ps4[i] = *(const float4*)&Ps[ty * 8 + i][kk4 * 4];
#pragma unroll
            for (int c = 0; c < 4; c++) {
                const int kk = kk4 * 4 + c;
                float4 v0 = *(const float4*)&Vs[kk][tx * 8];
                float4 v1 = *(const float4*)&Vs[kk][tx * 8 + 4];
                float vr[8] = {v0.x, v0.y, v0.z, v0.w, v1.x, v1.y, v1.z, v1.w};
                float pr[8];
#pragma unroll
                for (int i = 0; i < 8; i++)
                    pr[i] = (c == 0) ? ps4[i].x : (c == 1) ? ps4[i].y
                          : (c == 2) ? ps4[i].z : ps4[i].w;
#pragma unroll
                for (int i = 0; i < 8; i++)
#pragma unroll
                    for (int j = 0; j < 8; j++)
                        o[i][j] = fmaf(pr[i], vr[j], o[i][j]);
            }
        }
    }

    // ---- writeout ----
#pragma unroll
    for (int i = 0; i < 8; i++) {
        const float inv = 1.0f / l[i];
        const int row = qbase + ty * 8 + i;
        float* yp = g_y + (size_t)(b * SS + row) * CC + h * DD + tx * 8;
        float4 c0 = {o[i][0] * inv, o[i][1] * inv, o[i][2] * inv, o[i][3] * inv};
        float4 c1 = {o[i][4] * inv, o[i][5] * inv, o[i][6] * inv, o[i][7] * inv};
        *(float4*)yp = c0;
        *(float4*)(yp + 4) = c1;
    }
}

// ---------------------------------------------------------------------------
// Launch — kernel launches ONLY.
// ---------------------------------------------------------------------------
extern "C" void kernel_launch(void* const* d_in, const int* in_sizes, int n_in,
                              void* d_out, int out_size)
{
    const float* x     = (const float*)d_in[0];   // (B,S,C) = 8192x768
    const float* Wqkv  = (const float*)d_in[1];   // 768x2304
    const float* Wproj = (const float*)d_in[2];   // 768x768
    float* out = (float*)d_out;                   // (B,S,C)

    // 1. RoPE tables
    rope_tables_kernel<<<(SS * HALF_D + 255) / 256, 256>>>();

    // 2. QKV GEMM: (8192x768) @ (768x2304)
    {
        dim3 grid(C3 / 128, BSROWS / 128);
        sgemm_qkv_kernel<<<grid, 256>>>(x, Wqkv);
    }

    // 3. RoPE + split + transpose
    rope_split_kernel<<<(BB * SS * CC + 255) / 256, 256>>>();

    // 4. Flash attention (register-blocked + pipelined)
    {
        dim3 grid(SS / 64, BB * HH);
        attn_kernel<<<grid, 64>>>();
    }

    // 5. Output projection: (8192x768) @ (768x768)
    {
        dim3 grid(CC / 128, BSROWS / 128);
        sgemm_proj_kernel<<<grid, 256>>>(Wproj, out);
    }
}

// round 15
// speedup vs baseline: 1.3622x; 1.0227x over previous
#include <cuda_runtime.h>
#include <math.h>

// Problem constants
#define BB 4
#define SS 2048
#define CC 768
#define HH 12
#define DD 64
#define C3 2304
#define BSROWS (BB * SS)          // 8192
#define HALF_D 32

// ---------------------------------------------------------------------------
// Scratch (device globals; no allocations allowed)
// ---------------------------------------------------------------------------
__device__ float g_q[(size_t)BB * HH * SS * DD];        // (B,H,S,D)
__device__ float g_k[(size_t)BB * HH * SS * DD];
__device__ float g_v[(size_t)BB * HH * SS * DD];
__device__ float g_y[(size_t)BSROWS * CC];              // (B,S,C) pre-proj
__device__ float g_cos[SS * HALF_D];
__device__ float g_sin[SS * HALF_D];

// ---------------------------------------------------------------------------
// RoPE tables (mirrors reference fp32 math)
// ---------------------------------------------------------------------------
__global__ void rope_tables_kernel() {
    int idx = blockIdx.x * blockDim.x + threadIdx.x;
    if (idx >= SS * HALF_D) return;
    int s = idx >> 5;
    int i = idx & 31;
    float theta = 1.0f / powf(10000.0f, (float)i * (1.0f / 32.0f));
    float f = (float)s * theta;
    g_cos[idx] = cosf(f);
    g_sin[idx] = sinf(f);
}

// ---------------------------------------------------------------------------
// QKV GEMM with fused RoPE + split + transpose epilogue.
// C-tile 128x128, K-step 8, 8x8/thread, 256 threads, LDG prefetch pipeline.
// Each 128-col tile lies entirely within q, k, or v (768 % 128 == 0) and
// holds complete heads; rotate-half partner (d^32) lives in lane tx^4 = lane^4.
// ---------------------------------------------------------------------------
__global__ __launch_bounds__(256) void sgemm_qkv_fused_kernel(
    const float* __restrict__ A, const float* __restrict__ Bm)
{
    __shared__ float As[8][128];
    __shared__ float Bs[8][128];

    const int tid = threadIdx.x;
    const int m0 = blockIdx.y * 128;
    const int n0 = blockIdx.x * 128;
    const int N = C3, K = CC;

    const int arow = tid >> 1;
    const int acol = (tid & 1) * 4;
    const int brow = tid >> 5;
    const int bcol = (tid & 31) * 4;

    const int tx = tid & 15;
    const int ty = tid >> 4;

    float acc[8][8];
#pragma unroll
    for (int i = 0; i < 8; i++)
#pragma unroll
        for (int j = 0; j < 8; j++) acc[i][j] = 0.0f;

    const int ktiles = K >> 3;

    float4 av = *(const float4*)&A[(size_t)(m0 + arow) * K + acol];
    float4 bv = *(const float4*)&Bm[(size_t)brow * N + n0 + bcol];

    for (int kt = 0; kt < ktiles; kt++) {
        if (kt > 0) __syncthreads();

        As[acol + 0][arow] = av.x;
        As[acol + 1][arow] = av.y;
        As[acol + 2][arow] = av.z;
        As[acol + 3][arow] = av.w;
        *(float4*)&Bs[brow][bcol] = bv;
        __syncthreads();

        if (kt + 1 < ktiles) {
            const int k0 = (kt + 1) << 3;
            av = *(const float4*)&A[(size_t)(m0 + arow) * K + k0 + acol];
            bv = *(const float4*)&Bm[(size_t)(k0 + brow) * N + n0 + bcol];
        }

#pragma unroll
        for (int kk = 0; kk < 8; kk++) {
            float4 a0 = *(const float4*)&As[kk][ty * 8];
            float4 a1 = *(const float4*)&As[kk][ty * 8 + 4];
            float4 b0 = *(const float4*)&Bs[kk][tx * 8];
            float4 b1 = *(const float4*)&Bs[kk][tx * 8 + 4];
            float ar[8] = {a0.x, a0.y, a0.z, a0.w, a1.x, a1.y, a1.z, a1.w};
            float br[8] = {b0.x, b0.y, b0.z, b0.w, b1.x, b1.y, b1.z, b1.w};
#pragma unroll
            for (int i = 0; i < 8; i++)
#pragma unroll
                for (int j = 0; j < 8; j++)
                    acc[i][j] = fmaf(ar[i], br[j], acc[i][j]);
        }
    }

    // ---- fused epilogue: rope + split + transpose ----
    const int sect = n0 / CC;                 // 0=q, 1=k, 2=v (block-uniform)
    const int cs0 = (n0 % CC) + tx * 8;       // section-local col base
    const int h = cs0 >> 6;
    const int d0 = cs0 & 63;
    const float sgn = (d0 & 32) ? 1.0f : -1.0f;

#pragma unroll
    for (int i = 0; i < 8; i++) {
        const int row = m0 + ty * 8 + i;
        const int b = row >> 11;
        const int srow = row & 2047;
        const size_t off = ((size_t)(b * HH + h) * SS + srow) * DD + d0;
        if (sect == 2) {
            float4 c0 = {acc[i][0], acc[i][1], acc[i][2], acc[i][3]};
            float4 c1 = {acc[i][4], acc[i][5], acc[i][6], acc[i][7]};
            *(float4*)(g_v + off) = c0;
            *(float4*)(g_v + off + 4) = c1;
        } else {
            const float* ct = g_cos + srow * HALF_D + (d0 & 31);
            const float* st = g_sin + srow * HALF_D + (d0 & 31);
            float ov[8];
#pragma unroll
            for (int j = 0; j < 8; j++) {
                float part = __shfl_xor_sync(0xffffffffu, acc[i][j], 4);
                ov[j] = acc[i][j] * ct[j] + sgn * part * st[j];
            }
            float* dst = (sect == 0) ? g_q : g_k;
            float4 c0 = {ov[0], ov[1], ov[2], ov[3]};
            float4 c1 = {ov[4], ov[5], ov[6], ov[7]};
            *(float4*)(dst + off) = c0;
            *(float4*)(dst + off + 4) = c1;
        }
    }
}

// ---------------------------------------------------------------------------
// Output projection: plain SGEMM.
// ---------------------------------------------------------------------------
__global__ __launch_bounds__(256) void sgemm_proj_kernel(
    const float* __restrict__ Bm, float* __restrict__ Cm)
{
    __shared__ float As[8][128];
    __shared__ float Bs[8][128];

    const int tid = threadIdx.x;
    const int m0 = blockIdx.y * 128;
    const int n0 = blockIdx.x * 128;
    const int N = CC, K = CC;
    const float* A = g_y;

    const int arow = tid >> 1;
    const int acol = (tid & 1) * 4;
    const int brow = tid >> 5;
    const int bcol = (tid & 31) * 4;

    const int tx = tid & 15;
    const int ty = tid >> 4;

    float acc[8][8];
#pragma unroll
    for (int i = 0; i < 8; i++)
#pragma unroll
        for (int j = 0; j < 8; j++) acc[i][j] = 0.0f;

    const int ktiles = K >> 3;

    float4 av = *(const float4*)&A[(size_t)(m0 + arow) * K + acol];
    float4 bv = *(const float4*)&Bm[(size_t)brow * N + n0 + bcol];

    for (int kt = 0; kt < ktiles; kt++) {
        if (kt > 0) __syncthreads();

        As[acol + 0][arow] = av.x;
        As[acol + 1][arow] = av.y;
        As[acol + 2][arow] = av.z;
        As[acol + 3][arow] = av.w;
        *(float4*)&Bs[brow][bcol] = bv;
        __syncthreads();

        if (kt + 1 < ktiles) {
            const int k0 = (kt + 1) << 3;
            av = *(const float4*)&A[(size_t)(m0 + arow) * K + k0 + acol];
            bv = *(const float4*)&Bm[(size_t)(k0 + brow) * N + n0 + bcol];
        }

#pragma unroll
        for (int kk = 0; kk < 8; kk++) {
            float4 a0 = *(const float4*)&As[kk][ty * 8];
            float4 a1 = *(const float4*)&As[kk][ty * 8 + 4];
            float4 b0 = *(const float4*)&Bs[kk][tx * 8];
            float4 b1 = *(const float4*)&Bs[kk][tx * 8 + 4];
            float ar[8] = {a0.x, a0.y, a0.z, a0.w, a1.x, a1.y, a1.z, a1.w};
            float br[8] = {b0.x, b0.y, b0.z, b0.w, b1.x, b1.y, b1.z, b1.w};
#pragma unroll
            for (int i = 0; i < 8; i++)
#pragma unroll
                for (int j = 0; j < 8; j++)
                    acc[i][j] = fmaf(ar[i], br[j], acc[i][j]);
        }
    }

#pragma unroll
    for (int i = 0; i < 8; i++) {
        float* crow = Cm + (size_t)(m0 + ty * 8 + i) * N + n0 + tx * 8;
        float4 c0 = {acc[i][0], acc[i][1], acc[i][2], acc[i][3]};
        float4 c1 = {acc[i][4], acc[i][5], acc[i][6], acc[i][7]};
        *(float4*)crow = c0;
        *(float4*)(crow + 4) = c1;
    }
}

// ---------------------------------------------------------------------------
// Flash attention, fp32, register-blocked; PV via warp shuffle broadcast.
// Block = 64 threads (8 tx x 8 ty). Q-tile 64, key-tile 32.
// Row group of (tx,ty) = lanes (ty&3)*8 .. +7  (lane bits 3-4 = ty).
// ---------------------------------------------------------------------------
__global__ __launch_bounds__(64) void attn_kernel() {
    const int qt = gridDim.x - 1 - blockIdx.x;     // query tile (64 rows)
    const int bh = blockIdx.y;
    const int b = bh / HH;
    const int h = bh % HH;
    const int tid = threadIdx.x;
    const int tx = tid & 7;
    const int ty = tid >> 3;
    const int lane = tid & 31;
    const int krow = tid & 31;
    const int half = tid >> 5;

    __shared__ float Qt[64][64];   // [d][q]
    __shared__ float Kt[64][32];   // [d][k]
    __shared__ float Vs[32][68];   // [k][d]

    const size_t base = (size_t)bh * SS * DD;
    const float sc = 0.125f * 1.4426950408889634f;  // D^-0.5 * log2(e)

    // Load Q tile transposed (thread tid owns query row qt*64+tid)
    {
        const float4* qp = (const float4*)(g_q + base + (size_t)(qt * 64 + tid) * DD);
#pragma unroll
        for (int i = 0; i < 16; i++) {
            float4 v = qp[i];
            Qt[4 * i + 0][tid] = v.x * sc;
            Qt[4 * i + 1][tid] = v.y * sc;
            Qt[4 * i + 2][tid] = v.z * sc;
            Qt[4 * i + 3][tid] = v.w * sc;
        }
    }

    float o[8][8];
#pragma unroll
    for (int i = 0; i < 8; i++)
#pragma unroll
        for (int j = 0; j < 8; j++) o[i][j] = 0.0f;
    float m[8], l[8];
#pragma unroll
    for (int i = 0; i < 8; i++) { m[i] = -3.0e38f; l[i] = 0.0f; }

    const int ntiles = 2 * qt + 2;      // 32-key tiles
    const int qbase = qt * 64;

    for (int t = 0; t < ntiles; t++) {
        __syncthreads();               // previous tile's consumers done

        // Load K (transposed) and V tiles: 32 key rows, 2 warps x half-row
        {
            const float* kp = g_k + base + (size_t)(t * 32 + krow) * DD + half * 32;
            const float* vp = g_v + base + (size_t)(t * 32 + krow) * DD + half * 32;
#pragma unroll
            for (int i = 0; i < 8; i++) {
                float4 kv = *(const float4*)(kp + 4 * i);
                const int d = half * 32 + 4 * i;
                Kt[d + 0][krow] = kv.x;
                Kt[d + 1][krow] = kv.y;
                Kt[d + 2][krow] = kv.z;
                Kt[d + 3][krow] = kv.w;
                *(float4*)&Vs[krow][half * 32 + 4 * i] = *(const float4*)(vp + 4 * i);
            }
        }
        __syncthreads();

        // ---- QK^T: s[8q][4k] ----
        float s[8][4];
#pragma unroll
        for (int i = 0; i < 8; i++)
#pragma unroll
            for (int j = 0; j < 4; j++) s[i][j] = 0.0f;

#pragma unroll 4
        for (int kk = 0; kk < 64; kk++) {
            float4 a0 = *(const float4*)&Qt[kk][ty * 8];
            float4 a1 = *(const float4*)&Qt[kk][ty * 8 + 4];
            float4 bv = *(const float4*)&Kt[kk][tx * 4];
            float ar[8] = {a0.x, a0.y, a0.z, a0.w, a1.x, a1.y, a1.z, a1.w};
            float br[4] = {bv.x, bv.y, bv.z, bv.w};
#pragma unroll
            for (int i = 0; i < 8; i++)
#pragma unroll
                for (int j = 0; j < 4; j++)
                    s[i][j] = fmaf(ar[i], br[j], s[i][j]);
        }

        // ---- causal mask (partial only on last two tiles) ----
        if (t >= 2 * qt) {
            const int kb = t * 32 + tx * 4;
#pragma unroll
            for (int i = 0; i < 8; i++) {
                const int r = qbase + ty * 8 + i;
#pragma unroll
                for (int j = 0; j < 4; j++)
                    if (kb + j > r) s[i][j] = -3.0e38f;
            }
        }

        // ---- online softmax (8 lanes per row group) ----
#pragma unroll
        for (int i = 0; i < 8; i++) {
            float mx = fmaxf(fmaxf(s[i][0], s[i][1]), fmaxf(s[i][2], s[i][3]));
            mx = fmaxf(mx, __shfl_xor_sync(0xffffffffu, mx, 1));
            mx = fmaxf(mx, __shfl_xor_sync(0xffffffffu, mx, 2));
            mx = fmaxf(mx, __shfl_xor_sync(0xffffffffu, mx, 4));
            float mnew = fmaxf(m[i], mx);
            float cf = exp2f(m[i] - mnew);
            m[i] = mnew;
            float rs = 0.0f;
#pragma unroll
            for (int j = 0; j < 4; j++) {
                s[i][j] = exp2f(s[i][j] - mnew);
                rs += s[i][j];
            }
            rs += __shfl_xor_sync(0xffffffffu, rs, 1);
            rs += __shfl_xor_sync(0xffffffffu, rs, 2);
            rs += __shfl_xor_sync(0xffffffffu, rs, 4);
            l[i] = l[i] * cf + rs;
#pragma unroll
            for (int j = 0; j < 8; j++) o[i][j] *= cf;
        }

        // ---- PV via shuffle broadcast: o[8q][8d] += P[8q][32k] @ V[32k][8d]
        // Row group = 8 lanes with same ty; lane bits 3-4 encode ty -> keep them.
        for (int src = 0; src < 8; src++) {
            const int srcLane = (lane & 24) | src;
#pragma unroll
            for (int jp = 0; jp < 4; jp++) {
                const int kk = src * 4 + jp;
                float4 v0 = *(const float4*)&Vs[kk][tx * 8];
                float4 v1 = *(const float4*)&Vs[kk][tx * 8 + 4];
                float vr[8] = {v0.x, v0.y, v0.z, v0.w, v1.x, v1.y, v1.z, v1.w};
                float pr[8];
#pragma unroll
                for (int i = 0; i < 8; i++)
                    pr[i] = __shfl_sync(0xffffffffu, s[i][jp], srcLane, 32);
#pragma unroll
                for (int i = 0; i < 8; i++)
#pragma unroll
                    for (int j = 0; j < 8; j++)
                        o[i][j] = fmaf(pr[i], vr[j], o[i][j]);
            }
        }
    }

    // ---- writeout ----
#pragma unroll
    for (int i = 0; i < 8; i++) {
        const float inv = 1.0f / l[i];
        const int row = qbase + ty * 8 + i;
        float* yp = g_y + (size_t)(b * SS + row) * CC + h * DD + tx * 8;
        float4 c0 = {o[i][0] * inv, o[i][1] * inv, o[i][2] * inv, o[i][3] * inv};
        float4 c1 = {o[i][4] * inv, o[i][5] * inv, o[i][6] * inv, o[i][7] * inv};
        *(float4*)yp = c0;
        *(float4*)(yp + 4) = c1;
    }
}

// ---------------------------------------------------------------------------
// Launch — kernel launches ONLY.
// ---------------------------------------------------------------------------
extern "C" void kernel_launch(void* const* d_in, const int* in_sizes, int n_in,
                              void* d_out, int out_size)
{
    const float* x     = (const float*)d_in[0];   // (B,S,C) = 8192x768
    const float* Wqkv  = (const float*)d_in[1];   // 768x2304
    const float* Wproj = (const float*)d_in[2];   // 768x768
    float* out = (float*)d_out;                   // (B,S,C)

    // 1. RoPE tables (needed by fused gemm epilogue)
    rope_tables_kernel<<<(SS * HALF_D + 255) / 256, 256>>>();

    // 2. QKV GEMM with fused RoPE + split: x -> g_q/g_k/g_v
    {
        dim3 grid(C3 / 128, BSROWS / 128);
        sgemm_qkv_fused_kernel<<<grid, 256>>>(x, Wqkv);
    }

    // 3. Flash attention (shuffle-PV) -> g_y
    {
        dim3 grid(SS / 64, BB * HH);
        attn_kernel<<<grid, 64>>>();
    }

    // 4. Output projection: (8192x768) @ (768x768) -> out
    {
        dim3 grid(CC / 128, BSROWS / 128);
        sgemm_proj_kernel<<<grid, 256>>>(Wproj, out);
    }
}

// round 16
// speedup vs baseline: 1.3898x; 1.0202x over previous
#include <cuda_runtime.h>
#include <math.h>

// Problem constants
#define BB 4
#define SS 2048
#define CC 768
#define HH 12
#define DD 64
#define C3 2304
#define BSROWS (BB * SS)          // 8192
#define HALF_D 32

typedef unsigned long long u64;

// ---------------------------------------------------------------------------
// Packed fp32x2 helpers (sm_100 PTX; plain FMA-pipe ops, IEEE fp32 per lane)
// ---------------------------------------------------------------------------
__device__ __forceinline__ u64 bcast2(float x) {
    u64 r; asm("mov.b64 %0, {%1, %1};" : "=l"(r) : "f"(x)); return r;
}
__device__ __forceinline__ void fma2(u64& d, u64 a, u64 b) {
    asm("fma.rn.f32x2 %0, %1, %2, %3;" : "=l"(d) : "l"(a), "l"(b), "l"(d));
}
__device__ __forceinline__ void mul2(u64& d, u64 a, u64 b) {
    asm("mul.rn.f32x2 %0, %1, %2;" : "=l"(d) : "l"(a), "l"(b));
}
__device__ __forceinline__ float2 unp(u64 v) {
    float2 f; asm("mov.b64 {%0, %1}, %2;" : "=f"(f.x), "=f"(f.y) : "l"(v)); return f;
}

// ---------------------------------------------------------------------------
// Scratch (device globals; no allocations allowed)
// ---------------------------------------------------------------------------
__device__ float g_q[(size_t)BB * HH * SS * DD];        // (B,H,S,D)
__device__ float g_k[(size_t)BB * HH * SS * DD];
__device__ float g_v[(size_t)BB * HH * SS * DD];
__device__ float g_y[(size_t)BSROWS * CC];              // (B,S,C) pre-proj
__device__ float g_cos[SS * HALF_D];
__device__ float g_sin[SS * HALF_D];

// ---------------------------------------------------------------------------
// RoPE tables (mirrors reference fp32 math)
// ---------------------------------------------------------------------------
__global__ void rope_tables_kernel() {
    int idx = blockIdx.x * blockDim.x + threadIdx.x;
    if (idx >= SS * HALF_D) return;
    int s = idx >> 5;
    int i = idx & 31;
    float theta = 1.0f / powf(10000.0f, (float)i * (1.0f / 32.0f));
    float f = (float)s * theta;
    g_cos[idx] = cosf(f);
    g_sin[idx] = sinf(f);
}

// ---------------------------------------------------------------------------
// Shared SGEMM core with packed-f32x2 inner loop.
// C-tile 128x128, K-step 8, 8x8/thread (acc packed 8x4 u64), 256 threads.
// ---------------------------------------------------------------------------
__device__ __forceinline__ void sgemm_core(
    const float* __restrict__ A, const float* __restrict__ Bm,
    int N, int K, int m0, int n0, u64 (&acc2)[8][4])
{
    __shared__ float As[8][128];
    __shared__ float Bs[8][128];

    const int tid = threadIdx.x;
    const int arow = tid >> 1;
    const int acol = (tid & 1) * 4;
    const int brow = tid >> 5;
    const int bcol = (tid & 31) * 4;
    const int tx = tid & 15;
    const int ty = tid >> 4;

#pragma unroll
    for (int i = 0; i < 8; i++)
#pragma unroll
        for (int j = 0; j < 4; j++) acc2[i][j] = 0ULL;

    const int ktiles = K >> 3;

    float4 av = *(const float4*)&A[(size_t)(m0 + arow) * K + acol];
    float4 bv = *(const float4*)&Bm[(size_t)brow * N + n0 + bcol];

    for (int kt = 0; kt < ktiles; kt++) {
        if (kt > 0) __syncthreads();

        As[acol + 0][arow] = av.x;
        As[acol + 1][arow] = av.y;
        As[acol + 2][arow] = av.z;
        As[acol + 3][arow] = av.w;
        *(float4*)&Bs[brow][bcol] = bv;
        __syncthreads();

        if (kt + 1 < ktiles) {
            const int k0 = (kt + 1) << 3;
            av = *(const float4*)&A[(size_t)(m0 + arow) * K + k0 + acol];
            bv = *(const float4*)&Bm[(size_t)(k0 + brow) * N + n0 + bcol];
        }

#pragma unroll
        for (int kk = 0; kk < 8; kk++) {
            float4 a0 = *(const float4*)&As[kk][ty * 8];
            float4 a1 = *(const float4*)&As[kk][ty * 8 + 4];
            ulonglong2 bA = *(const ulonglong2*)&Bs[kk][tx * 8];
            ulonglong2 bB = *(const ulonglong2*)&Bs[kk][tx * 8 + 4];
            float ar[8] = {a0.x, a0.y, a0.z, a0.w, a1.x, a1.y, a1.z, a1.w};
#pragma unroll
            for (int i = 0; i < 8; i++) {
                u64 a2 = bcast2(ar[i]);
                fma2(acc2[i][0], a2, bA.x);
                fma2(acc2[i][1], a2, bA.y);
                fma2(acc2[i][2], a2, bB.x);
                fma2(acc2[i][3], a2, bB.y);
            }
        }
    }
}

// ---------------------------------------------------------------------------
// QKV GEMM with fused RoPE + split + transpose epilogue.
// ---------------------------------------------------------------------------
__global__ __launch_bounds__(256) void sgemm_qkv_fused_kernel(
    const float* __restrict__ A, const float* __restrict__ Bm)
{
    const int m0 = blockIdx.y * 128;
    const int n0 = blockIdx.x * 128;
    const int tid = threadIdx.x;
    const int tx = tid & 15;
    const int ty = tid >> 4;

    u64 acc2[8][4];
    sgemm_core(A, Bm, C3, CC, m0, n0, acc2);

    // ---- fused epilogue: rope + split + transpose ----
    const int sect = n0 / CC;                 // 0=q, 1=k, 2=v (block-uniform)
    const int cs0 = (n0 % CC) + tx * 8;       // section-local col base
    const int h = cs0 >> 6;
    const int d0 = cs0 & 63;
    const float sgn = (d0 & 32) ? 1.0f : -1.0f;

#pragma unroll
    for (int i = 0; i < 8; i++) {
        float2 p0 = unp(acc2[i][0]);
        float2 p1 = unp(acc2[i][1]);
        float2 p2 = unp(acc2[i][2]);
        float2 p3 = unp(acc2[i][3]);
        float accv[8] = {p0.x, p0.y, p1.x, p1.y, p2.x, p2.y, p3.x, p3.y};

        const int row = m0 + ty * 8 + i;
        const int b = row >> 11;
        const int srow = row & 2047;
        const size_t off = ((size_t)(b * HH + h) * SS + srow) * DD + d0;
        if (sect == 2) {
            float4 c0 = {accv[0], accv[1], accv[2], accv[3]};
            float4 c1 = {accv[4], accv[5], accv[6], accv[7]};
            *(float4*)(g_v + off) = c0;
            *(float4*)(g_v + off + 4) = c1;
        } else {
            const float* ct = g_cos + srow * HALF_D + (d0 & 31);
            const float* st = g_sin + srow * HALF_D + (d0 & 31);
            float ov[8];
#pragma unroll
            for (int j = 0; j < 8; j++) {
                float part = __shfl_xor_sync(0xffffffffu, accv[j], 4);
                ov[j] = accv[j] * ct[j] + sgn * part * st[j];
            }
            float* dst = (sect == 0) ? g_q : g_k;
            float4 c0 = {ov[0], ov[1], ov[2], ov[3]};
            float4 c1 = {ov[4], ov[5], ov[6], ov[7]};
            *(float4*)(dst + off) = c0;
            *(float4*)(dst + off + 4) = c1;
        }
    }
}

// ---------------------------------------------------------------------------
// Output projection: same core, plain epilogue.
// ---------------------------------------------------------------------------
__global__ __launch_bounds__(256) void sgemm_proj_kernel(
    const float* __restrict__ Bm, float* __restrict__ Cm)
{
    const int m0 = blockIdx.y * 128;
    const int n0 = blockIdx.x * 128;
    const int tid = threadIdx.x;
    const int tx = tid & 15;
    const int ty = tid >> 4;

    u64 acc2[8][4];
    sgemm_core(g_y, Bm, CC, CC, m0, n0, acc2);

#pragma unroll
    for (int i = 0; i < 8; i++) {
        float2 p0 = unp(acc2[i][0]);
        float2 p1 = unp(acc2[i][1]);
        float2 p2 = unp(acc2[i][2]);
        float2 p3 = unp(acc2[i][3]);
        float* crow = Cm + (size_t)(m0 + ty * 8 + i) * CC + n0 + tx * 8;
        float4 c0 = {p0.x, p0.y, p1.x, p1.y};
        float4 c1 = {p2.x, p2.y, p3.x, p3.y};
        *(float4*)crow = c0;
        *(float4*)(crow + 4) = c1;
    }
}

// ---------------------------------------------------------------------------
// Flash attention, fp32 packed-f32x2; PV via warp shuffle broadcast.
// Block = 64 threads (8 tx x 8 ty). Q-tile 64, key-tile 32.
// ---------------------------------------------------------------------------
__global__ __launch_bounds__(64) void attn_kernel() {
    const int qt = gridDim.x - 1 - blockIdx.x;     // query tile (64 rows)
    const int bh = blockIdx.y;
    const int b = bh / HH;
    const int h = bh % HH;
    const int tid = threadIdx.x;
    const int tx = tid & 7;
    const int ty = tid >> 3;
    const int lane = tid & 31;
    const int krow = tid & 31;
    const int half = tid >> 5;

    __shared__ float Qt[64][64];   // [d][q]
    __shared__ float Kt[64][32];   // [d][k]
    __shared__ float Vs[32][68];   // [k][d]

    const size_t base = (size_t)bh * SS * DD;
    const float sc = 0.125f * 1.4426950408889634f;  // D^-0.5 * log2(e)

    // Load Q tile transposed
    {
        const float4* qp = (const float4*)(g_q + base + (size_t)(qt * 64 + tid) * DD);
#pragma unroll
        for (int i = 0; i < 16; i++) {
            float4 v = qp[i];
            Qt[4 * i + 0][tid] = v.x * sc;
            Qt[4 * i + 1][tid] = v.y * sc;
            Qt[4 * i + 2][tid] = v.z * sc;
            Qt[4 * i + 3][tid] = v.w * sc;
        }
    }

    u64 o2[8][4];
#pragma unroll
    for (int i = 0; i < 8; i++)
#pragma unroll
        for (int j = 0; j < 4; j++) o2[i][j] = 0ULL;
    float m[8], l[8];
#pragma unroll
    for (int i = 0; i < 8; i++) { m[i] = -3.0e38f; l[i] = 0.0f; }

    const int ntiles = 2 * qt + 2;      // 32-key tiles
    const int qbase = qt * 64;

    for (int t = 0; t < ntiles; t++) {
        __syncthreads();

        // Load K (transposed) and V tiles
        {
            const float* kp = g_k + base + (size_t)(t * 32 + krow) * DD + half * 32;
            const float* vp = g_v + base + (size_t)(t * 32 + krow) * DD + half * 32;
#pragma unroll
            for (int i = 0; i < 8; i++) {
                float4 kv = *(const float4*)(kp + 4 * i);
                const int d = half * 32 + 4 * i;
                Kt[d + 0][krow] = kv.x;
                Kt[d + 1][krow] = kv.y;
                Kt[d + 2][krow] = kv.z;
                Kt[d + 3][krow] = kv.w;
                *(float4*)&Vs[krow][half * 32 + 4 * i] = *(const float4*)(vp + 4 * i);
            }
        }
        __syncthreads();

        // ---- QK^T packed: s2[8][2] over 4 keys ----
        u64 s2[8][2];
#pragma unroll
        for (int i = 0; i < 8; i++) { s2[i][0] = 0ULL; s2[i][1] = 0ULL; }

#pragma unroll 4
        for (int kk = 0; kk < 64; kk++) {
            float4 a0 = *(const float4*)&Qt[kk][ty * 8];
            float4 a1 = *(const float4*)&Qt[kk][ty * 8 + 4];
            ulonglong2 kb = *(const ulonglong2*)&Kt[kk][tx * 4];
            float ar[8] = {a0.x, a0.y, a0.z, a0.w, a1.x, a1.y, a1.z, a1.w};
#pragma unroll
            for (int i = 0; i < 8; i++) {
                u64 a2 = bcast2(ar[i]);
                fma2(s2[i][0], a2, kb.x);
                fma2(s2[i][1], a2, kb.y);
            }
        }

        // unpack scores
        float s[8][4];
#pragma unroll
        for (int i = 0; i < 8; i++) {
            float2 f0 = unp(s2[i][0]);
            float2 f1 = unp(s2[i][1]);
            s[i][0] = f0.x; s[i][1] = f0.y; s[i][2] = f1.x; s[i][3] = f1.y;
        }

        // ---- causal mask (partial only on last two tiles) ----
        if (t >= 2 * qt) {
            const int kb = t * 32 + tx * 4;
#pragma unroll
            for (int i = 0; i < 8; i++) {
                const int r = qbase + ty * 8 + i;
#pragma unroll
                for (int j = 0; j < 4; j++)
                    if (kb + j > r) s[i][j] = -3.0e38f;
            }
        }

        // ---- online softmax ----
#pragma unroll
        for (int i = 0; i < 8; i++) {
            float mx = fmaxf(fmaxf(s[i][0], s[i][1]), fmaxf(s[i][2], s[i][3]));
            mx = fmaxf(mx, __shfl_xor_sync(0xffffffffu, mx, 1));
            mx = fmaxf(mx, __shfl_xor_sync(0xffffffffu, mx, 2));
            mx = fmaxf(mx, __shfl_xor_sync(0xffffffffu, mx, 4));
            float mnew = fmaxf(m[i], mx);
            float cf = exp2f(m[i] - mnew);
            m[i] = mnew;
            float rs = 0.0f;
#pragma unroll
            for (int j = 0; j < 4; j++) {
                s[i][j] = exp2f(s[i][j] - mnew);
                rs += s[i][j];
            }
            rs += __shfl_xor_sync(0xffffffffu, rs, 1);
            rs += __shfl_xor_sync(0xffffffffu, rs, 2);
            rs += __shfl_xor_sync(0xffffffffu, rs, 4);
            l[i] = l[i] * cf + rs;
            u64 cf2 = bcast2(cf);
#pragma unroll
            for (int j = 0; j < 4; j++) mul2(o2[i][j], o2[i][j], cf2);
        }

        // ---- PV via shuffle broadcast, packed ----
        for (int src = 0; src < 8; src++) {
            const int srcLane = (lane & 24) | src;
#pragma unroll
            for (int jp = 0; jp < 4; jp++) {
                const int kk = src * 4 + jp;
                ulonglong2 vA = *(const ulonglong2*)&Vs[kk][tx * 8];
                ulonglong2 vB = *(const ulonglong2*)&Vs[kk][tx * 8 + 4];
                float pr[8];
#pragma unroll
                for (int i = 0; i < 8; i++)
                    pr[i] = __shfl_sync(0xffffffffu, s[i][jp], srcLane, 32);
#pragma unroll
                for (int i = 0; i < 8; i++) {
                    u64 p2 = bcast2(pr[i]);
                    fma2(o2[i][0], p2, vA.x);
                    fma2(o2[i][1], p2, vA.y);
                    fma2(o2[i][2], p2, vB.x);
                    fma2(o2[i][3], p2, vB.y);
                }
            }
        }
    }

    // ---- writeout ----
#pragma unroll
    for (int i = 0; i < 8; i++) {
        const float inv = 1.0f / l[i];
        const int row = qbase + ty * 8 + i;
        float2 p0 = unp(o2[i][0]);
        float2 p1 = unp(o2[i][1]);
        float2 p2 = unp(o2[i][2]);
        float2 p3 = unp(o2[i][3]);
        float* yp = g_y + (size_t)(b * SS + row) * CC + h * DD + tx * 8;
        float4 c0 = {p0.x * inv, p0.y * inv, p1.x * inv, p1.y * inv};
        float4 c1 = {p2.x * inv, p2.y * inv, p3.x * inv, p3.y * inv};
        *(float4*)yp = c0;
        *(float4*)(yp + 4) = c1;
    }
}

// ---------------------------------------------------------------------------
// Launch — kernel launches ONLY.
// ---------------------------------------------------------------------------
extern "C" void kernel_launch(void* const* d_in, const int* in_sizes, int n_in,
                              void* d_out, int out_size)
{
    const float* x     = (const float*)d_in[0];   // (B,S,C) = 8192x768
    const float* Wqkv  = (const float*)d_in[1];   // 768x2304
    const float* Wproj = (const float*)d_in[2];   // 768x768
    float* out = (float*)d_out;                   // (B,S,C)

    // 1. RoPE tables (needed by fused gemm epilogue)
    rope_tables_kernel<<<(SS * HALF_D + 255) / 256, 256>>>();

    // 2. QKV GEMM with fused RoPE + split: x -> g_q/g_k/g_v
    {
        dim3 grid(C3 / 128, BSROWS / 128);
        sgemm_qkv_fused_kernel<<<grid, 256>>>(x, Wqkv);
    }

    // 3. Flash attention (shuffle-PV, packed f32x2) -> g_y
    {
        dim3 grid(SS / 64, BB * HH);
        attn_kernel<<<grid, 64>>>();
    }

    // 4. Output projection: (8192x768) @ (768x768) -> out
    {
        dim3 grid(CC / 128, BSROWS / 128);
        sgemm_proj_kernel<<<grid, 256>>>(Wproj, out);
    }
}